// round 9
// baseline (speedup 1.0000x reference)
#include <cuda_runtime.h>
#include <cuda_bf16.h>
#include <cstdint>

// out[b, h] = verb_scores[b, idx[h]]
// BATCH = 131072, NUM_HOIS = 600, NUM_VERBS = 117, idx int32[600].
//
// Evolution: R2 flat (96.5us, L1 89.5%) -> R5 register-q persistent (72.9us,
// but 1200 blocks vs 888 resident = 1.48x wave penalty) -> R8 flat one-wave
// (68.8us, occ 97.5%, but idx reload pushed L1 back to 80.2%).
// R9 = register-q AND one-wave: grid 1125 (divisible by 75 so that
// threads % 150 == 0 -> fixed q per thread, indices live in registers),
// 1125 <= 1184 resident capacity -> single wave. L1 wf/512B: 24 -> 20.

#define NUM_VERBS 117
#define NUM_HOIS  600
#define QUADS_PER_ROW 150

#define THREADS 256
#define BLOCKS  1125   // 1125*256 = 288000 threads = 1920 rows/wave; <=1184 resident

__global__ __launch_bounds__(THREADS, 8) void scatter_verbs_kernel(
    const float* __restrict__ verb_scores,  // [BATCH, 117] fp32
    const int*   __restrict__ hoi_to_verb,  // [600] int32
    float*       __restrict__ out,          // [BATCH, 600] fp32
    int batch)
{
    const int g  = blockIdx.x * THREADS + threadIdx.x;
    const int q  = g % QUADS_PER_ROW;                        // fixed quad slot
    const int b0 = g / QUADS_PER_ROW;                        // starting row
    const int bstride = (BLOCKS * THREADS) / QUADS_PER_ROW;  // 1920

    // This thread's 4 indices, loaded ONCE into registers (16B-aligned int4).
    const int4 idx = __ldg(reinterpret_cast<const int4*>(hoi_to_verb) + q);

    int b = b0;
    // 2 rows per iteration: 8 independent gather LDGs in flight (MLP).
    for (; b + bstride < batch; b += 2 * bstride) {
        const float* rowA = verb_scores + (long long)b * NUM_VERBS;
        const float* rowB = verb_scores + (long long)(b + bstride) * NUM_VERBS;

        float4 va, vb;
        va.x = __ldg(&rowA[idx.x]);
        va.y = __ldg(&rowA[idx.y]);
        va.z = __ldg(&rowA[idx.z]);
        va.w = __ldg(&rowA[idx.w]);
        vb.x = __ldg(&rowB[idx.x]);
        vb.y = __ldg(&rowB[idx.y]);
        vb.z = __ldg(&rowB[idx.z]);
        vb.w = __ldg(&rowB[idx.w]);

        // Streaming stores: write-once 315 MB output, keep L2 for verb rows.
        __stcs(reinterpret_cast<float4*>(out + (long long)b * NUM_HOIS) + q, va);
        __stcs(reinterpret_cast<float4*>(out + (long long)(b + bstride) * NUM_HOIS) + q, vb);
    }
    for (; b < batch; b += bstride) {   // tail (threads with b0 < 512 take it)
        const float* row = verb_scores + (long long)b * NUM_VERBS;
        float4 v;
        v.x = __ldg(&row[idx.x]);
        v.y = __ldg(&row[idx.y]);
        v.z = __ldg(&row[idx.z]);
        v.w = __ldg(&row[idx.w]);
        __stcs(reinterpret_cast<float4*>(out + (long long)b * NUM_HOIS) + q, v);
    }
}

extern "C" void kernel_launch(void* const* d_in, const int* in_sizes, int n_in,
                              void* d_out, int out_size) {
    const float* verb_scores = (const float*)d_in[0];
    const int*   hoi_to_verb = (const int*)d_in[1];
    float* out = (float*)d_out;

    int batch = in_sizes[0] / NUM_VERBS;    // 131072

    scatter_verbs_kernel<<<BLOCKS, THREADS>>>(verb_scores, hoi_to_verb, out, batch);
}